// round 15
// baseline (speedup 1.0000x reference)
#include <cuda_runtime.h>
#include <cuda_fp16.h>
#include <math.h>

#define MDIM 128        // N_COMBOS (dual dim)
#define NDIM 512        // N_STRUCTS (primal dim)
#define HID  20
#define NITER 60
#define CONTROLF 10.0f
#define RCAP 40         // max row nnz (binomial mean 16)
#define CCAP 16         // max col nnz (binomial mean 4)
#define CCAPH 12        // max col nnz in a 64-row half
#define RJJ  (RCAP/4)
#define CJJ  (CCAP/4)
#define RROWS 4         // batch rows per CTA

// Raw adjacency lists (by actual id).
__device__ int            g_csr_rawn[MDIM];
__device__ unsigned short g_csr_raw[MDIM * RCAP];
__device__ int            g_csc_rawn[NDIM];
__device__ unsigned short g_csc_raw[NDIM * CCAP];
// CSC half-column partial lists (half h scans rows 64h..64h+63).
__device__ int            g_csc_rawn2[2 * NDIM];
__device__ unsigned short g_csc_raw2[2 * NDIM * CCAPH];

// Owner permutations (slot -> actual id), sorted by nnz for warp balance.
__device__ int g_rm[MDIM];
__device__ int g_rn[NDIM];

// Packed, transposed (by OWNER SLOT), zero-slot-padded index lists.
__device__ int     g_csr_cnt[MDIM];
__device__ ushort4 g_csr_pk[RJJ * MDIM];
__device__ int     g_csc_cnt[NDIM];
__device__ uchar4  g_csc_pk[CJJ * NDIM];
__device__ float   g_tau;

// ---------------------------------------------------------------------------
// Kernel 0a: raw structure build, wide + latency-hidden. 24 blocks x 128 thr.
// ---------------------------------------------------------------------------
__global__ void build_kernel(const float* __restrict__ S) {
    const int t = threadIdx.x;
    const int b = blockIdx.x;

    if (b < 8) {
        const int h = b >> 2;              // row half: 0 or 1
        const int n = (b & 3) * 128 + t;   // column
        const int base = 64 * h;
        int cnt = 0;
        for (int c0 = 0; c0 < 64; c0 += 16) {
            float vals[16];
            #pragma unroll
            for (int i = 0; i < 16; i++) vals[i] = S[(base + c0 + i) * NDIM + n];
            #pragma unroll
            for (int i = 0; i < 16; i++) {
                if (vals[i] != 0.0f) {
                    if (cnt < CCAPH)
                        g_csc_raw2[(h * NDIM + n) * CCAPH + cnt] =
                            (unsigned short)(base + c0 + i);
                    cnt++;
                }
            }
        }
        g_csc_rawn2[h * NDIM + n] = cnt < CCAPH ? cnt : CCAPH;
    } else {
        const int lane = t & 31;
        const int w    = t >> 5;
        const float4* S4 = reinterpret_cast<const float4*>(S);  // row = 128 float4
        for (int rr = 0; rr < 2; rr++) {
            const int m = (b - 8) * 8 + w * 2 + rr;
            float4 v[4];
            #pragma unroll
            for (int q = 0; q < 4; q++) v[q] = S4[m * 128 + q * 32 + lane];
            int c = 0;
            #pragma unroll
            for (int q = 0; q < 4; q++) {
                const float vv[4] = {v[q].x, v[q].y, v[q].z, v[q].w};
                #pragma unroll
                for (int comp = 0; comp < 4; comp++) {
                    const bool nz = (vv[comp] != 0.0f);
                    const unsigned mask = __ballot_sync(0xffffffffu, nz);
                    if (nz) {
                        const int pos = c + __popc(mask & ((1u << lane) - 1u));
                        if (pos < RCAP)
                            g_csr_raw[m * RCAP + pos] =
                                (unsigned short)(q * 128 + lane * 4 + comp);
                    }
                    c += __popc(mask);
                }
            }
            if (lane == 0) g_csr_rawn[m] = c < RCAP ? c : RCAP;
        }
    }
}

// ---------------------------------------------------------------------------
// Kernel 0b: concat CSC halves, counting-sort owners by nnz, repack by owner
// slot, then power iteration -> tau. One block, 512 threads.
// ---------------------------------------------------------------------------
__global__ void __launch_bounds__(512) pack_power_kernel() {
    const int t = threadIdx.x;   // 0..511

    {
        const int L0 = g_csc_rawn2[t];
        const int L1 = g_csc_rawn2[NDIM + t];
        int L = L0 + L1; if (L > CCAP) L = CCAP;
        for (int j = 0; j < L0 && j < CCAP; j++)
            g_csc_raw[t * CCAP + j] = g_csc_raw2[t * CCAPH + j];
        for (int j = 0; j < L1 && L0 + j < CCAP; j++)
            g_csc_raw[t * CCAP + L0 + j] = g_csc_raw2[(NDIM + t) * CCAPH + j];
        g_csc_rawn[t] = L;
    }
    __syncthreads();

    __shared__ int r_hist[64];
    __shared__ int c_hist[64];
    if (t < 64) { r_hist[t] = 0; c_hist[t] = 0; }
    __syncthreads();

    if (t < MDIM) atomicAdd(&r_hist[g_csr_rawn[t]], 1);
    atomicAdd(&c_hist[g_csc_rawn[t]], 1);
    __syncthreads();

    if (t == 0) { int s = 0; for (int k = 0; k < 64; k++) { int x = r_hist[k]; r_hist[k] = s; s += x; } }
    if (t == 1) { int s = 0; for (int k = 0; k < 64; k++) { int x = c_hist[k]; c_hist[k] = s; s += x; } }
    __syncthreads();

    if (t < MDIM) {
        const int pos = atomicAdd(&r_hist[g_csr_rawn[t]], 1);
        g_rm[pos] = t;
    }
    {
        const int pos = atomicAdd(&c_hist[g_csc_rawn[t]], 1);
        g_rn[pos] = t;
    }
    __syncthreads();

    if (t < MDIM) {
        const int m = g_rm[t];
        const int L = g_csr_rawn[m];
        unsigned short* pk = reinterpret_cast<unsigned short*>(g_csr_pk);
        for (int j = 0; j < L; j++)
            pk[((j >> 2) * MDIM + t) * 4 + (j & 3)] = g_csr_raw[m * RCAP + j];
        const int cnt4 = (L + 3) >> 2;
        for (int j = L; j < cnt4 * 4; j++)
            pk[((j >> 2) * MDIM + t) * 4 + (j & 3)] = (unsigned short)NDIM;
        g_csr_cnt[t] = cnt4;
    }
    {
        const int n = g_rn[t];
        const int L = g_csc_rawn[n];
        unsigned char* pk = reinterpret_cast<unsigned char*>(g_csc_pk);
        for (int j = 0; j < L; j++)
            pk[((j >> 2) * NDIM + t) * 4 + (j & 3)] = (unsigned char)g_csc_raw[n * CCAP + j];
        const int cnt4 = (L + 3) >> 2;
        for (int j = L; j < cnt4 * 4; j++)
            pk[((j >> 2) * NDIM + t) * 4 + (j & 3)] = (unsigned char)MDIM;
        g_csc_cnt[t] = cnt4;
    }
    __syncthreads();

    __shared__ float v[NDIM + 1];
    __shared__ float p[MDIM + 1];
    __shared__ float red[16];

    v[t] = 1.0f;
    if (t == 0) { v[NDIM] = 0.0f; p[MDIM] = 0.0f; }
    __syncthreads();

    const int myn  = g_rn[t];
    const int mym  = (t < MDIM) ? g_rm[t] : 0;
    const int ccnt = g_csc_cnt[t];
    float Lsq = 0.0f;

    for (int it = 0; it <= 30; it++) {
        if (t < MDIM) {
            float a = 0.0f;
            const int rc = g_csr_cnt[t];
            for (int jj = 0; jj < rc; jj++) {
                const ushort4 id = g_csr_pk[jj * MDIM + t];
                a += v[id.x] + v[id.y] + v[id.z] + v[id.w];
            }
            p[mym] = a;
        }
        __syncthreads();
        float a = v[myn];
        for (int jj = 0; jj < ccnt; jj++) {
            const uchar4 id = g_csc_pk[jj * NDIM + t];
            a += p[id.x] + p[id.y] + p[id.z] + p[id.w];
        }

        float s = (it == 30) ? (a * v[myn]) : (a * a);
        #pragma unroll
        for (int o = 16; o > 0; o >>= 1) s += __shfl_xor_sync(0xffffffffu, s, o);
        if ((t & 31) == 0) red[t >> 5] = s;
        __syncthreads();
        float tot = 0.0f;
        #pragma unroll
        for (int ww = 0; ww < 16; ww++) tot += red[ww];

        if (it == 30) { Lsq = tot; break; }
        v[myn] = a / sqrtf(tot);
        __syncthreads();
    }

    if (t == 0) g_tau = 0.9f / sqrtf(Lsq);
}

// ---------------------------------------------------------------------------
__device__ __forceinline__ float4 f4add(float4 a, float4 b) {
    return make_float4(a.x + b.x, a.y + b.y, a.z + b.z, a.w + b.w);
}
__device__ __forceinline__ __half2 ash2(unsigned u) {
    return *reinterpret_cast<const __half2*>(&u);
}
__device__ __forceinline__ unsigned h2u(__half2 h) {
    return *reinterpret_cast<const unsigned*>(&h);
}
__device__ __forceinline__ uint2 packh4(float4 v) {
    const __half2 lo = __floats2half2_rn(v.x, v.y);
    const __half2 hi = __floats2half2_rn(v.z, v.w);
    return make_uint2(h2u(lo), h2u(hi));
}
__device__ __forceinline__ float4 unpackh4(uint2 v) {
    const float2 lo = __half22float2(ash2(v.x));
    const float2 hi = __half22float2(ash2(v.y));
    return make_float4(lo.x, lo.y, hi.x, hi.y);
}
// 4-packet (single) accumulate: fp16 tree (6 HADD2) then fp32 add.
__device__ __forceinline__ void accq(float4& a, uint2 v0, uint2 v1,
                                     uint2 v2, uint2 v3) {
    const __half2 lo = __hadd2(__hadd2(ash2(v0.x), ash2(v1.x)),
                               __hadd2(ash2(v2.x), ash2(v3.x)));
    const __half2 hi = __hadd2(__hadd2(ash2(v0.y), ash2(v1.y)),
                               __hadd2(ash2(v2.y), ash2(v3.y)));
    const float2 flo = __half22float2(lo);
    const float2 fhi = __half22float2(hi);
    a.x += flo.x; a.y += flo.y; a.z += fhi.x; a.w += fhi.y;
}
// 8-packet (pair) accumulate: one deeper fp16 tree, half the converts/FADDs.
__device__ __forceinline__ void accp(float4& a,
                                     uint2 v0, uint2 v1, uint2 v2, uint2 v3,
                                     uint2 w0, uint2 w1, uint2 w2, uint2 w3) {
    const __half2 lo = __hadd2(
        __hadd2(__hadd2(ash2(v0.x), ash2(v1.x)), __hadd2(ash2(v2.x), ash2(v3.x))),
        __hadd2(__hadd2(ash2(w0.x), ash2(w1.x)), __hadd2(ash2(w2.x), ash2(w3.x))));
    const __half2 hi = __hadd2(
        __hadd2(__hadd2(ash2(v0.y), ash2(v1.y)), __hadd2(ash2(v2.y), ash2(v3.y))),
        __hadd2(__hadd2(ash2(w0.y), ash2(w1.y)), __hadd2(ash2(w2.y), ash2(w3.y))));
    const float2 flo = __half22float2(lo);
    const float2 fhi = __half22float2(hi);
    a.x += flo.x; a.y += flo.y; a.z += fhi.x; a.w += fhi.y;
}

// ---------------------------------------------------------------------------
// Kernel 1: fused MLP + 60-iteration PDHG. 4 batch rows per CTA, 128 threads.
// lam2 and the register copy of xb are packed fp16 (uint2); z/x fp32.
// ---------------------------------------------------------------------------
__global__ void __launch_bounds__(128) solve_kernel(
    const float* __restrict__ X,
    const float* __restrict__ W1, const float* __restrict__ B1,
    const float* __restrict__ W2, const float* __restrict__ B2,
    const float* __restrict__ W3, const float* __restrict__ B3,
    const float* __restrict__ W4, const float* __restrict__ B4,
    float* __restrict__ out)
{
    const int row0 = blockIdx.x * RROWS;
    const int t    = threadIdx.x;   // 0..127

    __shared__ float4 bx_sh[MDIM];
    __shared__ uint2  xbH[NDIM + 1];     // packed 4xfp16 by actual n, zero slot
    __shared__ uint2  lam1H[MDIM + 1];   // packed 4xfp16 by actual m, zero slot
    __shared__ float  h_sh[RROWS][HID + 4];
    __shared__ float4 red[4];

    {
        float4 v;
        v.x = X[(row0 + 0) * MDIM + t];
        v.y = X[(row0 + 1) * MDIM + t];
        v.z = X[(row0 + 2) * MDIM + t];
        v.w = X[(row0 + 3) * MDIM + t];
        bx_sh[t] = v;
    }
    if (t == 0) {
        xbH[NDIM]   = make_uint2(0u, 0u);
        lam1H[MDIM] = make_uint2(0u, 0u);
    }
    const int mym = g_rm[t];
    int rn[4];
    #pragma unroll
    for (int k = 0; k < 4; k++) rn[k] = g_rn[t + 128 * k];
    __syncthreads();

    // ---- MLP (threads 0..79 = (row r, unit i)) ----
    if (t < RROWS * HID) {
        const int r = t / HID, i = t % HID;
        float a = B1[i];
        for (int k = 0; k < MDIM; k++)
            a += ((const float*)&bx_sh[k])[r] * W1[k * HID + i];
        h_sh[r][i] = tanhf(a);
    }
    __syncthreads();
    {
        float a = 0.0f;
        if (t < RROWS * HID) {
            const int r = t / HID, i = t % HID;
            a = B2[i];
            #pragma unroll
            for (int k = 0; k < HID; k++) a += h_sh[r][k] * W2[k * HID + i];
            a = tanhf(a);
        }
        __syncthreads();
        if (t < RROWS * HID) h_sh[t / HID][t % HID] = a;
        __syncthreads();
        if (t < RROWS * HID) {
            const int r = t / HID, i = t % HID;
            a = B3[i];
            #pragma unroll
            for (int k = 0; k < HID; k++) a += h_sh[r][k] * W3[k * HID + i];
            a = tanhf(a);
        }
        __syncthreads();
        if (t < RROWS * HID) h_sh[t / HID][t % HID] = a;
        __syncthreads();
    }

    float4 z[4], x[4];
    uint2  lam2p[4], xbp[4];
    #pragma unroll
    for (int k = 0; k < 4; k++) {
        const int n = rn[k];
        const float b4v = B4[n];
        float4 a = make_float4(b4v, b4v, b4v, b4v);
        #pragma unroll
        for (int j = 0; j < HID; j++) {
            const float w = W4[j * NDIM + n];
            a.x += h_sh[0][j] * w;
            a.y += h_sh[1][j] * w;
            a.z += h_sh[2][j] * w;
            a.w += h_sh[3][j] * w;
        }
        z[k] = a;
        x[k] = make_float4(fmaxf(a.x, 0.f), fmaxf(a.y, 0.f),
                           fmaxf(a.z, 0.f), fmaxf(a.w, 0.f));
        lam2p[k] = make_uint2(0u, 0u);
        xbp[k] = packh4(x[k]);
        xbH[n] = xbp[k];
    }

    const float tau = g_tau;                  // sig == tau
    const __half2 tauh  = __float2half2_rn(tau);
    const __half2 zeroh = __float2half2_rn(0.0f);
    float4 lam1r = make_float4(0.f, 0.f, 0.f, 0.f);
    lam1H[mym] = make_uint2(0u, 0u);
    const float4 b4 = bx_sh[mym];
    const float4 taub = make_float4(tau * b4.x, tau * b4.y,
                                    tau * b4.z, tau * b4.w);
    const int rcnt = g_csr_cnt[t];
    int cc[4];
    #pragma unroll
    for (int k = 0; k < 4; k++) cc[k] = g_csc_cnt[t + 128 * k];
    __syncthreads();

    // ---- PDHG mainloop ----
    for (int it = 0; it < NITER; it++) {
        // dual 1: lam1 = max(lam1 + sig*(S xb) - sig*b, 0)
        {
            float4 acc = make_float4(0.f, 0.f, 0.f, 0.f);
            int jj = 0;
            for (; jj + 2 <= rcnt; jj += 2) {
                const ushort4 i0 = g_csr_pk[jj * MDIM + t];        // coalesced
                const ushort4 i1 = g_csr_pk[(jj + 1) * MDIM + t];  // coalesced
                accp(acc,
                     xbH[i0.x], xbH[i0.y], xbH[i0.z], xbH[i0.w],
                     xbH[i1.x], xbH[i1.y], xbH[i1.z], xbH[i1.w]);
            }
            if (jj < rcnt) {
                const ushort4 id = g_csr_pk[jj * MDIM + t];
                accq(acc, xbH[id.x], xbH[id.y], xbH[id.z], xbH[id.w]);
            }
            lam1r.x = fmaxf(fmaf(tau, acc.x, lam1r.x) - taub.x, 0.f);
            lam1r.y = fmaxf(fmaf(tau, acc.y, lam1r.y) - taub.y, 0.f);
            lam1r.z = fmaxf(fmaf(tau, acc.z, lam1r.z) - taub.z, 0.f);
            lam1r.w = fmaxf(fmaf(tau, acc.w, lam1r.w) - taub.w, 0.f);
            lam1H[mym] = packh4(lam1r);
        }
        // dual 2 (packed fp16): lam2 = min(lam2 + tau*xb, 0)
        #pragma unroll
        for (int k = 0; k < 4; k++) {
            lam2p[k].x = h2u(__hmin2(__hfma2(tauh, ash2(xbp[k].x),
                                             ash2(lam2p[k].x)), zeroh));
            lam2p[k].y = h2u(__hmin2(__hfma2(tauh, ash2(xbp[k].y),
                                             ash2(lam2p[k].y)), zeroh));
        }
        __syncthreads();

        // primal: u = x - tau*(S^T lam1 + lam2) + tau - z
        float4 u[4];
        float4 ss = make_float4(0.f, 0.f, 0.f, 0.f);
        #pragma unroll
        for (int k = 0; k < 4; k++) {
            const int cnt = cc[k];
            float4 ca = unpackh4(lam2p[k]);      // seed accumulator with lam2
            for (int jj = 0; jj < cnt; jj++) {
                const uchar4 id = g_csc_pk[jj * NDIM + (t + 128 * k)];  // coalesced
                accq(ca, lam1H[id.x], lam1H[id.y], lam1H[id.z], lam1H[id.w]);
            }
            u[k].x = (x[k].x - tau * ca.x) + tau - z[k].x;
            u[k].y = (x[k].y - tau * ca.y) + tau - z[k].y;
            u[k].z = (x[k].z - tau * ca.z) + tau - z[k].z;
            u[k].w = (x[k].w - tau * ca.w) + tau - z[k].w;
            ss.x += u[k].x * u[k].x;
            ss.y += u[k].y * u[k].y;
            ss.z += u[k].z * u[k].z;
            ss.w += u[k].w * u[k].w;
        }

        // block reduce ||u||^2 per row over 128 threads (4 warps)
        #pragma unroll
        for (int o = 16; o > 0; o >>= 1) {
            ss.x += __shfl_xor_sync(0xffffffffu, ss.x, o);
            ss.y += __shfl_xor_sync(0xffffffffu, ss.y, o);
            ss.z += __shfl_xor_sync(0xffffffffu, ss.z, o);
            ss.w += __shfl_xor_sync(0xffffffffu, ss.w, o);
        }
        if ((t & 31) == 0) red[t >> 5] = ss;
        __syncthreads();
        {
            const float4 tot = f4add(f4add(red[0], red[1]), f4add(red[2], red[3]));
            const float tc = tau * CONTROLF;
            float4 sc;
            sc.x = fmaxf(0.f, 1.f - tc / fmaxf(sqrtf(tot.x), 1e-12f));
            sc.y = fmaxf(0.f, 1.f - tc / fmaxf(sqrtf(tot.y), 1e-12f));
            sc.z = fmaxf(0.f, 1.f - tc / fmaxf(sqrtf(tot.z), 1e-12f));
            sc.w = fmaxf(0.f, 1.f - tc / fmaxf(sqrtf(tot.w), 1e-12f));

            #pragma unroll
            for (int k = 0; k < 4; k++) {
                float4 xn;
                xn.x = fmaf(sc.x, u[k].x, z[k].x);
                xn.y = fmaf(sc.y, u[k].y, z[k].y);
                xn.z = fmaf(sc.z, u[k].z, z[k].z);
                xn.w = fmaf(sc.w, u[k].w, z[k].w);
                float4 nb;
                nb.x = 2.f * xn.x - x[k].x;
                nb.y = 2.f * xn.y - x[k].y;
                nb.z = 2.f * xn.z - x[k].z;
                nb.w = 2.f * xn.w - x[k].w;
                x[k] = xn;
                xbp[k] = packh4(nb);
                xbH[rn[k]] = xbp[k];
            }
        }
        __syncthreads();
    }

    #pragma unroll
    for (int k = 0; k < 4; k++) {
        const int n = rn[k];
        out[(row0 + 0) * NDIM + n] = x[k].x;
        out[(row0 + 1) * NDIM + n] = x[k].y;
        out[(row0 + 2) * NDIM + n] = x[k].z;
        out[(row0 + 3) * NDIM + n] = x[k].w;
    }
}

// ---------------------------------------------------------------------------
extern "C" void kernel_launch(void* const* d_in, const int* in_sizes, int n_in,
                              void* d_out, int out_size) {
    const float* X  = (const float*)d_in[0];
    const float* W1 = (const float*)d_in[1];
    const float* B1 = (const float*)d_in[2];
    const float* W2 = (const float*)d_in[3];
    const float* B2 = (const float*)d_in[4];
    const float* W3 = (const float*)d_in[5];
    const float* B3 = (const float*)d_in[6];
    const float* W4 = (const float*)d_in[7];
    const float* B4 = (const float*)d_in[8];
    const float* S  = (const float*)d_in[9];
    const int batch = in_sizes[0] / MDIM;

    build_kernel<<<24, 128>>>(S);
    pack_power_kernel<<<1, NDIM>>>();
    solve_kernel<<<batch / RROWS, 128>>>(X, W1, B1, W2, B2, W3, B3, W4, B4,
                                         (float*)d_out);
}

// round 16
// speedup vs baseline: 1.0263x; 1.0263x over previous
#include <cuda_runtime.h>
#include <cuda_fp16.h>
#include <math.h>

#define MDIM 128        // N_COMBOS (dual dim)
#define NDIM 512        // N_STRUCTS (primal dim)
#define HID  20
#define NITER 60
#define CONTROLF 10.0f
#define RCAP 40         // max row nnz (binomial mean 16)
#define CCAP 16         // max col nnz (binomial mean 4)
#define CCAPH 12        // max col nnz in a 64-row half
#define RJJ  (RCAP/4)
#define CJJ  (CCAP/4)
#define RROWS 4         // batch rows per CTA

// Raw adjacency lists (by actual id).
__device__ int            g_csr_rawn[MDIM];
__device__ unsigned short g_csr_raw[MDIM * RCAP];
__device__ int            g_csc_rawn[NDIM];
__device__ unsigned short g_csc_raw[NDIM * CCAP];
// CSC half-column partial lists (half h scans rows 64h..64h+63).
__device__ int            g_csc_rawn2[2 * NDIM];
__device__ unsigned short g_csc_raw2[2 * NDIM * CCAPH];

// Owner permutations (slot -> actual id), sorted by nnz for warp balance.
__device__ int g_rm[MDIM];
__device__ int g_rn[NDIM];

// Packed, transposed (by OWNER SLOT), zero-slot-padded index lists.
__device__ int     g_csr_cnt[MDIM];
__device__ ushort4 g_csr_pk[RJJ * MDIM];
__device__ int     g_csc_cnt[NDIM];
__device__ uchar4  g_csc_pk[CJJ * NDIM];
__device__ float   g_tau;

// ---------------------------------------------------------------------------
// Kernel 0a: raw structure build, wide + latency-hidden. 24 blocks x 128 thr.
// ---------------------------------------------------------------------------
__global__ void build_kernel(const float* __restrict__ S) {
    const int t = threadIdx.x;
    const int b = blockIdx.x;

    if (b < 8) {
        const int h = b >> 2;              // row half: 0 or 1
        const int n = (b & 3) * 128 + t;   // column
        const int base = 64 * h;
        int cnt = 0;
        for (int c0 = 0; c0 < 64; c0 += 16) {
            float vals[16];
            #pragma unroll
            for (int i = 0; i < 16; i++) vals[i] = S[(base + c0 + i) * NDIM + n];
            #pragma unroll
            for (int i = 0; i < 16; i++) {
                if (vals[i] != 0.0f) {
                    if (cnt < CCAPH)
                        g_csc_raw2[(h * NDIM + n) * CCAPH + cnt] =
                            (unsigned short)(base + c0 + i);
                    cnt++;
                }
            }
        }
        g_csc_rawn2[h * NDIM + n] = cnt < CCAPH ? cnt : CCAPH;
    } else {
        const int lane = t & 31;
        const int w    = t >> 5;
        const float4* S4 = reinterpret_cast<const float4*>(S);  // row = 128 float4
        for (int rr = 0; rr < 2; rr++) {
            const int m = (b - 8) * 8 + w * 2 + rr;
            float4 v[4];
            #pragma unroll
            for (int q = 0; q < 4; q++) v[q] = S4[m * 128 + q * 32 + lane];
            int c = 0;
            #pragma unroll
            for (int q = 0; q < 4; q++) {
                const float vv[4] = {v[q].x, v[q].y, v[q].z, v[q].w};
                #pragma unroll
                for (int comp = 0; comp < 4; comp++) {
                    const bool nz = (vv[comp] != 0.0f);
                    const unsigned mask = __ballot_sync(0xffffffffu, nz);
                    if (nz) {
                        const int pos = c + __popc(mask & ((1u << lane) - 1u));
                        if (pos < RCAP)
                            g_csr_raw[m * RCAP + pos] =
                                (unsigned short)(q * 128 + lane * 4 + comp);
                    }
                    c += __popc(mask);
                }
            }
            if (lane == 0) g_csr_rawn[m] = c < RCAP ? c : RCAP;
        }
    }
}

// ---------------------------------------------------------------------------
// Kernel 0b: concat CSC halves, counting-sort owners by nnz, repack by owner
// slot, then power iteration -> tau. One block, 512 threads.
// ---------------------------------------------------------------------------
__global__ void __launch_bounds__(512) pack_power_kernel() {
    const int t = threadIdx.x;   // 0..511

    {
        const int L0 = g_csc_rawn2[t];
        const int L1 = g_csc_rawn2[NDIM + t];
        int L = L0 + L1; if (L > CCAP) L = CCAP;
        for (int j = 0; j < L0 && j < CCAP; j++)
            g_csc_raw[t * CCAP + j] = g_csc_raw2[t * CCAPH + j];
        for (int j = 0; j < L1 && L0 + j < CCAP; j++)
            g_csc_raw[t * CCAP + L0 + j] = g_csc_raw2[(NDIM + t) * CCAPH + j];
        g_csc_rawn[t] = L;
    }
    __syncthreads();

    __shared__ int r_hist[64];
    __shared__ int c_hist[64];
    if (t < 64) { r_hist[t] = 0; c_hist[t] = 0; }
    __syncthreads();

    if (t < MDIM) atomicAdd(&r_hist[g_csr_rawn[t]], 1);
    atomicAdd(&c_hist[g_csc_rawn[t]], 1);
    __syncthreads();

    if (t == 0) { int s = 0; for (int k = 0; k < 64; k++) { int x = r_hist[k]; r_hist[k] = s; s += x; } }
    if (t == 1) { int s = 0; for (int k = 0; k < 64; k++) { int x = c_hist[k]; c_hist[k] = s; s += x; } }
    __syncthreads();

    if (t < MDIM) {
        const int pos = atomicAdd(&r_hist[g_csr_rawn[t]], 1);
        g_rm[pos] = t;
    }
    {
        const int pos = atomicAdd(&c_hist[g_csc_rawn[t]], 1);
        g_rn[pos] = t;
    }
    __syncthreads();

    if (t < MDIM) {
        const int m = g_rm[t];
        const int L = g_csr_rawn[m];
        unsigned short* pk = reinterpret_cast<unsigned short*>(g_csr_pk);
        for (int j = 0; j < L; j++)
            pk[((j >> 2) * MDIM + t) * 4 + (j & 3)] = g_csr_raw[m * RCAP + j];
        const int cnt4 = (L + 3) >> 2;
        for (int j = L; j < cnt4 * 4; j++)
            pk[((j >> 2) * MDIM + t) * 4 + (j & 3)] = (unsigned short)NDIM;
        g_csr_cnt[t] = cnt4;
    }
    {
        const int n = g_rn[t];
        const int L = g_csc_rawn[n];
        unsigned char* pk = reinterpret_cast<unsigned char*>(g_csc_pk);
        for (int j = 0; j < L; j++)
            pk[((j >> 2) * NDIM + t) * 4 + (j & 3)] = (unsigned char)g_csc_raw[n * CCAP + j];
        const int cnt4 = (L + 3) >> 2;
        for (int j = L; j < cnt4 * 4; j++)
            pk[((j >> 2) * NDIM + t) * 4 + (j & 3)] = (unsigned char)MDIM;
        g_csc_cnt[t] = cnt4;
    }
    __syncthreads();

    __shared__ float v[NDIM + 1];
    __shared__ float p[MDIM + 1];
    __shared__ float red[16];

    v[t] = 1.0f;
    if (t == 0) { v[NDIM] = 0.0f; p[MDIM] = 0.0f; }
    __syncthreads();

    const int myn  = g_rn[t];
    const int mym  = (t < MDIM) ? g_rm[t] : 0;
    const int ccnt = g_csc_cnt[t];
    float Lsq = 0.0f;

    for (int it = 0; it <= 30; it++) {
        if (t < MDIM) {
            float a = 0.0f;
            const int rc = g_csr_cnt[t];
            for (int jj = 0; jj < rc; jj++) {
                const ushort4 id = g_csr_pk[jj * MDIM + t];
                a += v[id.x] + v[id.y] + v[id.z] + v[id.w];
            }
            p[mym] = a;
        }
        __syncthreads();
        float a = v[myn];
        for (int jj = 0; jj < ccnt; jj++) {
            const uchar4 id = g_csc_pk[jj * NDIM + t];
            a += p[id.x] + p[id.y] + p[id.z] + p[id.w];
        }

        float s = (it == 30) ? (a * v[myn]) : (a * a);
        #pragma unroll
        for (int o = 16; o > 0; o >>= 1) s += __shfl_xor_sync(0xffffffffu, s, o);
        if ((t & 31) == 0) red[t >> 5] = s;
        __syncthreads();
        float tot = 0.0f;
        #pragma unroll
        for (int ww = 0; ww < 16; ww++) tot += red[ww];

        if (it == 30) { Lsq = tot; break; }
        v[myn] = a / sqrtf(tot);
        __syncthreads();
    }

    if (t == 0) g_tau = 0.9f / sqrtf(Lsq);
}

// ---------------------------------------------------------------------------
__device__ __forceinline__ float4 f4add(float4 a, float4 b) {
    return make_float4(a.x + b.x, a.y + b.y, a.z + b.z, a.w + b.w);
}
__device__ __forceinline__ __half2 ash2(unsigned u) {
    return *reinterpret_cast<const __half2*>(&u);
}
__device__ __forceinline__ unsigned h2u(__half2 h) {
    return *reinterpret_cast<const unsigned*>(&h);
}
__device__ __forceinline__ uint2 packh4(float4 v) {
    const __half2 lo = __floats2half2_rn(v.x, v.y);
    const __half2 hi = __floats2half2_rn(v.z, v.w);
    return make_uint2(h2u(lo), h2u(hi));
}
// 4-packet (single) accumulate: fp16 tree (6 HADD2) then fp32 add.
__device__ __forceinline__ void accq(float4& a, uint2 v0, uint2 v1,
                                     uint2 v2, uint2 v3) {
    const __half2 lo = __hadd2(__hadd2(ash2(v0.x), ash2(v1.x)),
                               __hadd2(ash2(v2.x), ash2(v3.x)));
    const __half2 hi = __hadd2(__hadd2(ash2(v0.y), ash2(v1.y)),
                               __hadd2(ash2(v2.y), ash2(v3.y)));
    const float2 flo = __half22float2(lo);
    const float2 fhi = __half22float2(hi);
    a.x += flo.x; a.y += flo.y; a.z += fhi.x; a.w += fhi.y;
}
// 8-packet (pair) accumulate: one deeper fp16 tree, half the converts/FADDs.
__device__ __forceinline__ void accp(float4& a,
                                     uint2 v0, uint2 v1, uint2 v2, uint2 v3,
                                     uint2 w0, uint2 w1, uint2 w2, uint2 w3) {
    const __half2 lo = __hadd2(
        __hadd2(__hadd2(ash2(v0.x), ash2(v1.x)), __hadd2(ash2(v2.x), ash2(v3.x))),
        __hadd2(__hadd2(ash2(w0.x), ash2(w1.x)), __hadd2(ash2(w2.x), ash2(w3.x))));
    const __half2 hi = __hadd2(
        __hadd2(__hadd2(ash2(v0.y), ash2(v1.y)), __hadd2(ash2(v2.y), ash2(v3.y))),
        __hadd2(__hadd2(ash2(w0.y), ash2(w1.y)), __hadd2(ash2(w2.y), ash2(w3.y))));
    const float2 flo = __half22float2(lo);
    const float2 fhi = __half22float2(hi);
    a.x += flo.x; a.y += flo.y; a.z += fhi.x; a.w += fhi.y;
}

// ---------------------------------------------------------------------------
// Kernel 1: fused MLP + 60-iteration PDHG. 4 batch rows per CTA, 128 threads.
// Thread t owns dual row g_rm[t] and primal cols g_rn[t+128k] (nnz-balanced).
// Gathered arrays (xb, lam1) packed 4xfp16; state fp32 in registers.
// ---------------------------------------------------------------------------
__global__ void __launch_bounds__(128) solve_kernel(
    const float* __restrict__ X,
    const float* __restrict__ W1, const float* __restrict__ B1,
    const float* __restrict__ W2, const float* __restrict__ B2,
    const float* __restrict__ W3, const float* __restrict__ B3,
    const float* __restrict__ W4, const float* __restrict__ B4,
    float* __restrict__ out)
{
    const int row0 = blockIdx.x * RROWS;
    const int t    = threadIdx.x;   // 0..127

    __shared__ float4 bx_sh[MDIM];
    __shared__ uint2  xbH[NDIM + 1];     // packed 4xfp16 by actual n, zero slot
    __shared__ uint2  lam1H[MDIM + 1];   // packed 4xfp16 by actual m, zero slot
    __shared__ float  h_sh[RROWS][HID + 4];
    __shared__ float4 red[4];

    {
        float4 v;
        v.x = X[(row0 + 0) * MDIM + t];
        v.y = X[(row0 + 1) * MDIM + t];
        v.z = X[(row0 + 2) * MDIM + t];
        v.w = X[(row0 + 3) * MDIM + t];
        bx_sh[t] = v;
    }
    if (t == 0) {
        xbH[NDIM]   = make_uint2(0u, 0u);
        lam1H[MDIM] = make_uint2(0u, 0u);
    }
    const int mym = g_rm[t];
    int rn[4];
    #pragma unroll
    for (int k = 0; k < 4; k++) rn[k] = g_rn[t + 128 * k];
    __syncthreads();

    // ---- MLP (threads 0..79 = (row r, unit i)) ----
    if (t < RROWS * HID) {
        const int r = t / HID, i = t % HID;
        float a = B1[i];
        for (int k = 0; k < MDIM; k++)
            a += ((const float*)&bx_sh[k])[r] * W1[k * HID + i];
        h_sh[r][i] = tanhf(a);
    }
    __syncthreads();
    {
        float a = 0.0f;
        if (t < RROWS * HID) {
            const int r = t / HID, i = t % HID;
            a = B2[i];
            #pragma unroll
            for (int k = 0; k < HID; k++) a += h_sh[r][k] * W2[k * HID + i];
            a = tanhf(a);
        }
        __syncthreads();
        if (t < RROWS * HID) h_sh[t / HID][t % HID] = a;
        __syncthreads();
        if (t < RROWS * HID) {
            const int r = t / HID, i = t % HID;
            a = B3[i];
            #pragma unroll
            for (int k = 0; k < HID; k++) a += h_sh[r][k] * W3[k * HID + i];
            a = tanhf(a);
        }
        __syncthreads();
        if (t < RROWS * HID) h_sh[t / HID][t % HID] = a;
        __syncthreads();
    }

    float4 z[4], x[4], lam2[4], xb[4];
    #pragma unroll
    for (int k = 0; k < 4; k++) {
        const int n = rn[k];
        const float b4v = B4[n];
        float4 a = make_float4(b4v, b4v, b4v, b4v);
        #pragma unroll
        for (int j = 0; j < HID; j++) {
            const float w = W4[j * NDIM + n];
            a.x += h_sh[0][j] * w;
            a.y += h_sh[1][j] * w;
            a.z += h_sh[2][j] * w;
            a.w += h_sh[3][j] * w;
        }
        z[k] = a;
        x[k] = make_float4(fmaxf(a.x, 0.f), fmaxf(a.y, 0.f),
                           fmaxf(a.z, 0.f), fmaxf(a.w, 0.f));
        lam2[k] = make_float4(0.f, 0.f, 0.f, 0.f);
        xb[k] = x[k];
        xbH[n] = packh4(x[k]);
    }

    const float tau = g_tau;                  // sig == tau
    float4 lam1r = make_float4(0.f, 0.f, 0.f, 0.f);
    lam1H[mym] = make_uint2(0u, 0u);
    const float4 b4 = bx_sh[mym];
    const float4 taub = make_float4(tau * b4.x, tau * b4.y,
                                    tau * b4.z, tau * b4.w);
    const int rcnt = g_csr_cnt[t];
    int cc[4];
    #pragma unroll
    for (int k = 0; k < 4; k++) cc[k] = g_csc_cnt[t + 128 * k];
    __syncthreads();

    // ---- PDHG mainloop ----
    for (int it = 0; it < NITER; it++) {
        // dual 1: lam1 = max(lam1 + sig*(S xb) - sig*b, 0)
        {
            float4 acc = make_float4(0.f, 0.f, 0.f, 0.f);
            int jj = 0;
            for (; jj + 2 <= rcnt; jj += 2) {
                const ushort4 i0 = g_csr_pk[jj * MDIM + t];        // coalesced
                const ushort4 i1 = g_csr_pk[(jj + 1) * MDIM + t];  // coalesced
                accp(acc,
                     xbH[i0.x], xbH[i0.y], xbH[i0.z], xbH[i0.w],
                     xbH[i1.x], xbH[i1.y], xbH[i1.z], xbH[i1.w]);
            }
            if (jj < rcnt) {
                const ushort4 id = g_csr_pk[jj * MDIM + t];
                accq(acc, xbH[id.x], xbH[id.y], xbH[id.z], xbH[id.w]);
            }
            lam1r.x = fmaxf(fmaf(tau, acc.x, lam1r.x) - taub.x, 0.f);
            lam1r.y = fmaxf(fmaf(tau, acc.y, lam1r.y) - taub.y, 0.f);
            lam1r.z = fmaxf(fmaf(tau, acc.z, lam1r.z) - taub.z, 0.f);
            lam1r.w = fmaxf(fmaf(tau, acc.w, lam1r.w) - taub.w, 0.f);
            lam1H[mym] = packh4(lam1r);
        }
        // dual 2 (registers only, exact fp32)
        #pragma unroll
        for (int k = 0; k < 4; k++) {
            lam2[k].x = fminf(fmaf(tau, xb[k].x, lam2[k].x), 0.f);
            lam2[k].y = fminf(fmaf(tau, xb[k].y, lam2[k].y), 0.f);
            lam2[k].z = fminf(fmaf(tau, xb[k].z, lam2[k].z), 0.f);
            lam2[k].w = fminf(fmaf(tau, xb[k].w, lam2[k].w), 0.f);
        }
        __syncthreads();

        // primal: u = x - tau*(S^T lam1 + lam2) + tau - z
        float4 u[4];
        float4 ss = make_float4(0.f, 0.f, 0.f, 0.f);
        #pragma unroll
        for (int k = 0; k < 4; k++) {
            const int cnt = cc[k];
            float4 ca = make_float4(0.f, 0.f, 0.f, 0.f);
            for (int jj = 0; jj < cnt; jj++) {
                const uchar4 id = g_csc_pk[jj * NDIM + (t + 128 * k)];  // coalesced
                accq(ca, lam1H[id.x], lam1H[id.y], lam1H[id.z], lam1H[id.w]);
            }
            u[k].x = (x[k].x - tau * (ca.x + lam2[k].x)) + tau - z[k].x;
            u[k].y = (x[k].y - tau * (ca.y + lam2[k].y)) + tau - z[k].y;
            u[k].z = (x[k].z - tau * (ca.z + lam2[k].z)) + tau - z[k].z;
            u[k].w = (x[k].w - tau * (ca.w + lam2[k].w)) + tau - z[k].w;
            ss.x += u[k].x * u[k].x;
            ss.y += u[k].y * u[k].y;
            ss.z += u[k].z * u[k].z;
            ss.w += u[k].w * u[k].w;
        }

        // block reduce ||u||^2 per row over 128 threads (4 warps)
        #pragma unroll
        for (int o = 16; o > 0; o >>= 1) {
            ss.x += __shfl_xor_sync(0xffffffffu, ss.x, o);
            ss.y += __shfl_xor_sync(0xffffffffu, ss.y, o);
            ss.z += __shfl_xor_sync(0xffffffffu, ss.z, o);
            ss.w += __shfl_xor_sync(0xffffffffu, ss.w, o);
        }
        if ((t & 31) == 0) red[t >> 5] = ss;
        __syncthreads();
        {
            const float4 tot = f4add(f4add(red[0], red[1]), f4add(red[2], red[3]));
            const float tc = tau * CONTROLF;
            // sc = max(0, 1 - tc/max(sqrt(tot),1e-12)) via rsqrt (no FP div).
            // tot -> 0 gives rsqrt -> inf -> sc clamps to 0, matching the
            // reference's guarded branch for degenerate norms.
            float4 sc;
            sc.x = fmaxf(0.f, 1.f - tc * rsqrtf(fmaxf(tot.x, 1e-24f)));
            sc.y = fmaxf(0.f, 1.f - tc * rsqrtf(fmaxf(tot.y, 1e-24f)));
            sc.z = fmaxf(0.f, 1.f - tc * rsqrtf(fmaxf(tot.z, 1e-24f)));
            sc.w = fmaxf(0.f, 1.f - tc * rsqrtf(fmaxf(tot.w, 1e-24f)));

            #pragma unroll
            for (int k = 0; k < 4; k++) {
                float4 xn;
                xn.x = fmaf(sc.x, u[k].x, z[k].x);
                xn.y = fmaf(sc.y, u[k].y, z[k].y);
                xn.z = fmaf(sc.z, u[k].z, z[k].z);
                xn.w = fmaf(sc.w, u[k].w, z[k].w);
                float4 nb;
                nb.x = 2.f * xn.x - x[k].x;
                nb.y = 2.f * xn.y - x[k].y;
                nb.z = 2.f * xn.z - x[k].z;
                nb.w = 2.f * xn.w - x[k].w;
                x[k] = xn;
                xb[k] = nb;
                xbH[rn[k]] = packh4(nb);
            }
        }
        __syncthreads();
    }

    #pragma unroll
    for (int k = 0; k < 4; k++) {
        const int n = rn[k];
        out[(row0 + 0) * NDIM + n] = x[k].x;
        out[(row0 + 1) * NDIM + n] = x[k].y;
        out[(row0 + 2) * NDIM + n] = x[k].z;
        out[(row0 + 3) * NDIM + n] = x[k].w;
    }
}

// ---------------------------------------------------------------------------
extern "C" void kernel_launch(void* const* d_in, const int* in_sizes, int n_in,
                              void* d_out, int out_size) {
    const float* X  = (const float*)d_in[0];
    const float* W1 = (const float*)d_in[1];
    const float* B1 = (const float*)d_in[2];
    const float* W2 = (const float*)d_in[3];
    const float* B2 = (const float*)d_in[4];
    const float* W3 = (const float*)d_in[5];
    const float* B3 = (const float*)d_in[6];
    const float* W4 = (const float*)d_in[7];
    const float* B4 = (const float*)d_in[8];
    const float* S  = (const float*)d_in[9];
    const int batch = in_sizes[0] / MDIM;

    build_kernel<<<24, 128>>>(S);
    pack_power_kernel<<<1, NDIM>>>();
    solve_kernel<<<batch / RROWS, 128>>>(X, W1, B1, W2, B2, W3, B3, W4, B4,
                                         (float*)d_out);
}